// round 17
// baseline (speedup 1.0000x reference)
#include <cuda_runtime.h>
#include <cuda_fp16.h>
#include <math.h>
#include <stdint.h>
#include <string.h>

// Problem dims (fixed by the reference)
#define Bq 4
#define Sq 2048
#define Eq 1024
#define Hn 16
#define Dd 64
#define BSq (Bq*Sq)      // 8192 rows
#define FEq (4*Eq)       // 4096 MLP hidden
#define QKVN 3072        // fused QKV output width
#define QT 64            // query tile for attention
#define NT (Sq/QT)       // 32 tiles
#define IDXS_T 1024      // max union keys per tile

// ---------------- scratch (no allocations allowed) ----------------
__device__ float g_h   [(size_t)BSq*Eq];    // ln1 fp32 (residual)
__device__ float g_hr  [(size_t)BSq*Eq];    // ln1 as half, reinterpreted
__device__ float g_qkv [(size_t)BSq*QKVN];  // fused qkv as HALF, reinterpreted
__device__ float g_attn[(size_t)BSq*Eq];    // attention out as half, reinterpreted
__device__ float g_t   [(size_t)BSq*Eq];    // ln2 as half, reinterpreted
__device__ float g_u   [(size_t)BSq*FEq];   // gelu out as half, reinterpreted
__device__ float g_w   [(size_t)12*1024*1024]; // weights as half (24M halves)
__device__ float g_bias[QKVN];              // combined qkv bias (scaled bq)
__device__ int g_tile_idx[(size_t)NT*IDXS_T];
__device__ unsigned long long g_tile_bits[(size_t)NT*IDXS_T];
__device__ int g_tile_cnt[NT];

// ---------------- helpers ----------------
__device__ __forceinline__ float fast_ex2(float x) {
    float y; asm("ex2.approx.f32 %0, %1;" : "=f"(y) : "f"(x)); return y;
}
__device__ __forceinline__ float fast_tanh(float x) {
    float y; asm("tanh.approx.f32 %0, %1;" : "=f"(y) : "f"(x)); return y;
}
__device__ __forceinline__ void cpa16(uint32_t dst, const void* src) {
    asm volatile("cp.async.ca.shared.global [%0], [%1], 16;" :: "r"(dst), "l"(src));
}
template<int N> __device__ __forceinline__ void cp_wait() {
    asm volatile("cp.async.wait_group %0;" :: "n"(N) : "memory");
}
__device__ __forceinline__ void cp_commit() {
    asm volatile("cp.async.commit_group;" ::: "memory");
}
__device__ __forceinline__ void mma16816(float* c, uint32_t a0, uint32_t a1,
                                         uint32_t a2, uint32_t a3,
                                         uint32_t b0, uint32_t b1) {
    asm volatile(
        "mma.sync.aligned.m16n8k16.row.col.f32.f16.f16.f32 "
        "{%0,%1,%2,%3}, {%4,%5,%6,%7}, {%8,%9}, {%0,%1,%2,%3};"
        : "+f"(c[0]), "+f"(c[1]), "+f"(c[2]), "+f"(c[3])
        : "r"(a0), "r"(a1), "r"(a2), "r"(a3), "r"(b0), "r"(b1));
}
__device__ __forceinline__ void ldsm_x4(uint32_t* r, uint32_t addr) {
    asm volatile("ldmatrix.sync.aligned.m8n8.x4.shared.b16 {%0,%1,%2,%3}, [%4];"
        : "=r"(r[0]), "=r"(r[1]), "=r"(r[2]), "=r"(r[3]) : "r"(addr));
}
// packed fp32 FMA: d(2xf32) += a(2xf32) * b(2xf32)
__device__ __forceinline__ void ffma2(unsigned long long& d, unsigned long long a,
                                      unsigned long long b) {
    asm("fma.rn.f32x2 %0, %1, %2, %0;" : "+l"(d) : "l"(a), "l"(b));
}

// ---------------- fused fp16 weight conversion + qkv bias combine ------------
__global__ void convert_w_kernel(const float* __restrict__ wq, const float* __restrict__ wk,
                                 const float* __restrict__ wv, const float* __restrict__ wo,
                                 const float* __restrict__ wfc, const float* __restrict__ wpr,
                                 const float* __restrict__ bq, const float* __restrict__ bk,
                                 const float* __restrict__ bv,
                                 __half* __restrict__ dst) {
    int i = blockIdx.x * blockDim.x + threadIdx.x;   // float4 index, total 3M
    // side job: combined qkv bias (768 float4 = 3072 floats)
    if (i < 768) {
        float4 bv4;
        if      (i < 256) { bv4 = ((const float4*)bq)[i];
                            bv4.x *= 0.125f; bv4.y *= 0.125f;
                            bv4.z *= 0.125f; bv4.w *= 0.125f; }
        else if (i < 512)   bv4 = ((const float4*)bk)[i - 256];
        else                bv4 = ((const float4*)bv)[i - 512];
        ((float4*)g_bias)[i] = bv4;
    }
    const int Q1 = 256 * 1024;
    const float4* src;
    int off;
    float sc = 1.f;
    if      (i <     Q1) { src = (const float4*)wq;  off = i;          sc = 0.125f; }
    else if (i < 2 * Q1) { src = (const float4*)wk;  off = i - Q1; }
    else if (i < 3 * Q1) { src = (const float4*)wv;  off = i - 2 * Q1; }
    else if (i < 4 * Q1) { src = (const float4*)wo;  off = i - 3 * Q1; }
    else if (i < 8 * Q1) { src = (const float4*)wfc; off = i - 4 * Q1; }
    else                 { src = (const float4*)wpr; off = i - 8 * Q1; }
    float4 v = src[off];
    __half2 lo = __floats2half2_rn(v.x * sc, v.y * sc);
    __half2 hi = __floats2half2_rn(v.z * sc, v.w * sc);
    uint32_t lo_u, hi_u;
    memcpy(&lo_u, &lo, 4);
    memcpy(&hi_u, &hi, 4);
    ((uint2*)dst)[i] = make_uint2(lo_u, hi_u);
}

// ---------------- per-tile union key list + row bitmaps (reads raw mask) ------
__global__ void tile_build_kernel(const unsigned char* __restrict__ m) {
    __shared__ unsigned long long sBits[Sq];
    int tile = blockIdx.x;
    int q0 = tile * QT;
    bool is_byte = (m[2048] != 0);   // mask[1][0]==True in byte layout
    const int* mi = (const int*)m;
    for (int col = threadIdx.x; col < Sq; col += blockDim.x) {
        unsigned long long bits = 0ULL;
        if (is_byte) {
            #pragma unroll 8
            for (int r = 0; r < QT; r++)
                bits |= (unsigned long long)(m[(size_t)(q0 + r) * Sq + col] != 0) << r;
        } else {
            #pragma unroll 8
            for (int r = 0; r < QT; r++)
                bits |= (unsigned long long)(mi[(size_t)(q0 + r) * Sq + col] != 0) << r;
        }
        sBits[col] = bits;
    }
    __syncthreads();
    if (threadIdx.x < 32) {
        int lane = threadIdx.x;
        int cnt = 0;
        for (int c0 = 0; c0 < Sq; c0 += 32) {
            unsigned long long bv = sBits[c0 + lane];
            unsigned msk = __ballot_sync(0xffffffffu, bv != 0ULL);
            int pos = cnt + __popc(msk & ((1u << lane) - 1u));
            if (bv) {
                g_tile_idx [(size_t)tile * IDXS_T + pos] = c0 + lane;
                g_tile_bits[(size_t)tile * IDXS_T + pos] = bv;
            }
            cnt += __popc(msk);
        }
        if (lane == 0) g_tile_cnt[tile] = cnt;
    }
}

// ---------------- layernorm (vectorized: 256 threads x 1 float4) --------------
__global__ void ln_kernel(const float* __restrict__ x, const float* __restrict__ g,
                          const float* __restrict__ b, float* __restrict__ out,
                          __half* __restrict__ out_h) {
    int row = blockIdx.x;
    int tid = threadIdx.x;
    const float4* xr4 = (const float4*)(x + (size_t)row * Eq);
    float4 v4 = xr4[tid];
    float s  = v4.x + v4.y + v4.z + v4.w;
    float s2 = v4.x * v4.x + v4.y * v4.y + v4.z * v4.z + v4.w * v4.w;

    __shared__ float sh[64];
    #pragma unroll
    for (int o = 16; o; o >>= 1) {
        s  += __shfl_xor_sync(0xffffffffu, s,  o);
        s2 += __shfl_xor_sync(0xffffffffu, s2, o);
    }
    int wid = tid >> 5, nl = tid & 31;
    if (nl == 0) { sh[wid] = s; sh[32 + wid] = s2; }
    __syncthreads();
    if (wid == 0) {
        s  = (nl < 8) ? sh[nl] : 0.f;
        s2 = (nl < 8) ? sh[32 + nl] : 0.f;
        #pragma unroll
        for (int o = 4; o; o >>= 1) {
            s  += __shfl_xor_sync(0xffffffffu, s,  o);
            s2 += __shfl_xor_sync(0xffffffffu, s2, o);
        }
        if (nl == 0) { sh[0] = s; sh[1] = s2; }
    }
    __syncthreads();
    float mean = sh[0] * (1.f / Eq);
    float var  = sh[1] * (1.f / Eq) - mean * mean;
    float rstd = rsqrtf(var + 1e-5f);

    float4 g4 = ((const float4*)g)[tid];
    float4 b4 = ((const float4*)b)[tid];
    float4 o4;
    o4.x = (v4.x - mean) * rstd * g4.x + b4.x;
    o4.y = (v4.y - mean) * rstd * g4.y + b4.y;
    o4.z = (v4.z - mean) * rstd * g4.z + b4.z;
    o4.w = (v4.w - mean) * rstd * g4.w + b4.w;
    if (out) ((float4*)(out + (size_t)row * Eq))[tid] = o4;
    if (out_h) {
        __half2 h0 = __floats2half2_rn(o4.x, o4.y);
        __half2 h1 = __floats2half2_rn(o4.z, o4.w);
        uint32_t u0, u1;
        memcpy(&u0, &h0, 4);
        memcpy(&u1, &h1, 4);
        ((uint2*)(out_h + (size_t)row * Eq))[tid] = make_uint2(u0, u1);
    }
}

// ---------------- fp16 mma.sync GEMM: C = epi( A[M,K] @ B[N,K]^T ) ------------
// 256 threads (8 warps), block tile 128(M)x256(N), warp tile 64x64,
// BK=128 halves, 2-stage cp.async (204KB smem), ONE __syncthreads per chunk,
// prefetch overlapped with compute, register double-buffered ldmatrix frags.
#define HSTR 136
#define STG_H (384*HSTR)              // halves per stage (128 A rows + 256 B rows)
#define GEMM_SMEM (2*STG_H*2)         // 208896 bytes

__global__ __launch_bounds__(256, 1)
void gemm_f16_kernel(const __half* __restrict__ A, const __half* __restrict__ Bmat,
                     const float* __restrict__ bias, const float* __restrict__ res,
                     float* __restrict__ Cf, __half* __restrict__ Ch,
                     int M, int N, int K, int do_gelu)
{
    extern __shared__ __half smh[];
    const uint32_t sbase = (uint32_t)__cvta_generic_to_shared(smh);

    int tid = threadIdx.x;
    int bm = blockIdx.y * 128, bn = blockIdx.x * 256;
    int warp = tid >> 5, lane = tid & 31;
    int g = lane >> 2, tig = lane & 3;
    int m0 = (warp >> 2) * 64, n0 = (warp & 3) * 64;   // warp tile 64x64

    int qm = lane >> 3, rr = lane & 7;
    uint32_t aOff[4], bOff[4];
    #pragma unroll
    for (int mt = 0; mt < 4; mt++)
        aOff[mt] = (uint32_t)(((m0 + mt * 16 + (qm & 1) * 8 + rr) * HSTR
                               + (qm >> 1) * 8) * 2);
    #pragma unroll
    for (int p = 0; p < 4; p++)
        bOff[p] = (uint32_t)(((128 + n0 + p * 16 + (qm >> 1) * 8 + rr) * HSTR
                               + (qm & 1) * 8) * 2);

    // global loads: 384 rows x 16 16B-chunks = 6144 cp.async per stage, 24/thread
    const __half* gsrc[24];
    uint32_t gdof[24];
    #pragma unroll
    for (int j = 0; j < 24; j++) {
        int id = tid + j * 256;
        int row = id >> 4, ch = id & 15;
        if (row < 128) gsrc[j] = A    + (size_t)(bm + row) * K + ch * 8;
        else           gsrc[j] = Bmat + (size_t)(bn + row - 128) * K + ch * 8;
        gdof[j] = (uint32_t)((row * HSTR + ch * 8) * 2);
    }

    float ac[4][8][4];
    #pragma unroll
    for (int i = 0; i < 4; i++)
        #pragma unroll
        for (int j = 0; j < 8; j++)
            #pragma unroll
            for (int l = 0; l < 4; l++) ac[i][j][l] = 0.f;

    int T = K / 128;
    // prologue: stage 0
    {
        #pragma unroll
        for (int j = 0; j < 24; j++)
            cpa16(sbase + gdof[j], gsrc[j]);
        cp_commit();
    }

    for (int c = 0; c < T; c++) {
        cp_wait<0>();        // stage c fully resident
        __syncthreads();     // all warps past their reads of the other stage

        // prefetch chunk c+1 into the other stage; overlaps with compute below
        if (c + 1 < T) {
            uint32_t soff = sbase + (uint32_t)(((c + 1) & 1) * STG_H) * 2u;
            #pragma unroll
            for (int j = 0; j < 24; j++)
                cpa16(soff + gdof[j], gsrc[j] + (c + 1) * 128);
            cp_commit();
        }

        uint32_t sstage = sbase + (uint32_t)((c & 1) * STG_H) * 2u;
        // register double-buffered fragments across the 8 k-steps
        uint32_t af[2][4][4], bf[2][4][4];
        #pragma unroll
        for (int mt = 0; mt < 4; mt++) ldsm_x4(af[0][mt], sstage + aOff[mt]);
        #pragma unroll
        for (int p = 0; p < 4; p++)    ldsm_x4(bf[0][p], sstage + bOff[p]);
        #pragma unroll
        for (int ks = 0; ks < 8; ks++) {
            int cur = ks & 1, nxt = cur ^ 1;
            if (ks < 7) {
                uint32_t koff = sstage + (ks + 1) * 32;
                #pragma unroll
                for (int mt = 0; mt < 4; mt++) ldsm_x4(af[nxt][mt], koff + aOff[mt]);
                #pragma unroll
                for (int p = 0; p < 4; p++)    ldsm_x4(bf[nxt][p], koff + bOff[p]);
            }
            #pragma unroll
            for (int mt = 0; mt < 4; mt++) {
                #pragma unroll
                for (int nt = 0; nt < 8; nt++) {
                    int p = nt >> 1, o = (nt & 1) * 2;
                    mma16816(ac[mt][nt], af[cur][mt][0], af[cur][mt][1],
                             af[cur][mt][2], af[cur][mt][3],
                             bf[cur][p][o], bf[cur][p][o + 1]);
                }
            }
        }
    }

    const float cgelu = 0.7978845608028654f;
    #pragma unroll
    for (int mt = 0; mt < 4; mt++) {
        #pragma unroll
        for (int hf = 0; hf < 2; hf++) {
            int r = bm + m0 + mt * 16 + g + hf * 8;
            #pragma unroll
            for (int nt = 0; nt < 8; nt++) {
                int cc = bn + n0 + nt * 8 + 2 * tig;
                float v0 = ac[mt][nt][hf * 2 + 0] + bias[cc];
                float v1 = ac[mt][nt][hf * 2 + 1] + bias[cc + 1];
                if (do_gelu) {
                    float i0 = cgelu * (v0 + 0.044715f * v0 * v0 * v0);
                    float i1 = cgelu * (v1 + 0.044715f * v1 * v1 * v1);
                    v0 = 0.5f * v0 * (1.f + fast_tanh(i0));
                    v1 = 0.5f * v1 * (1.f + fast_tanh(i1));
                }
                if (res) {
                    v0 += res[(size_t)r * N + cc];
                    v1 += res[(size_t)r * N + cc + 1];
                }
                if (Cf) *(float2*)(Cf + (size_t)r * N + cc) = make_float2(v0, v1);
                if (Ch) {
                    __half2 hv = __floats2half2_rn(v0, v1);
                    *(__half2*)(Ch + (size_t)r * N + cc) = hv;
                }
            }
        }
    }
}

// ---------------- tiled sparse attention (half qkv in; half out) --------------
// PROVEN structure (R11/R15/R16): block = (tile, h, b); 8 warps.
#define ATT_SMEM 66304

__global__ __launch_bounds__(256)
void attn_tile_kernel(const __half* __restrict__ qkvh, __half* __restrict__ out)
{
    const float LOG2E = 1.4426950408889634f;
    extern __shared__ float smA[];
    float* sQ  = smA;                       // [64 q][64 d]
    float* sKI = smA + 4096;                // [32 d2][65 key-pairs] x2 floats
    float* sV  = smA + 8256;                // [64 key][64 d]
    float* sP  = smA + 12352;               // [8 warp][64 key][8 q]
    unsigned long long* sBits = (unsigned long long*)(smA + 16448);

    int tile = blockIdx.x, h = blockIdx.y, b = blockIdx.z;
    int q0 = tile * QT;
    int tid = threadIdx.x, warp = tid >> 5, lane = tid & 31;
    int wq0 = warp * 8;
    float* sPw = sP + warp * 512;

    for (int i = tid; i < QT * 8; i += 256) {
        int r = i >> 3, ch = i & 7;
        uint4 raw = *(const uint4*)(qkvh + (size_t)(b * Sq + q0 + r) * QKVN + h * 64 + ch * 8);
        __half2 hh[4];
        memcpy(hh, &raw, 16);
        float2 f0 = __half22float2(hh[0]);
        float2 f1 = __half22float2(hh[1]);
        float2 f2 = __half22float2(hh[2]);
        float2 f3 = __half22float2(hh[3]);
        *(float4*)&sQ[r * 64 + ch * 8]     = make_float4(f0.x, f0.y, f1.x, f1.y);
        *(float4*)&sQ[r * 64 + ch * 8 + 4] = make_float4(f2.x, f2.y, f3.x, f3.y);
    }

    int cnt = g_tile_cnt[tile];
    const int* idx = g_tile_idx + (size_t)tile * IDXS_T;
    const unsigned long long* tb = g_tile_bits + (size_t)tile * IDXS_T;

    float la[8], acc[8][2];
    #pragma unroll
    for (int qq = 0; qq < 8; qq++) { la[qq] = 0.f; acc[qq][0] = 0.f; acc[qq][1] = 0.f; }

    for (int c0 = 0; c0 < cnt; c0 += 64) {
        __syncthreads();
        for (int i = tid; i < 64 * 8; i += 256) {
            int j = i >> 3, ch = i & 7;
            int kk = (c0 + j < cnt) ? idx[c0 + j] : 0;
            size_t base = (size_t)(b * Sq + kk) * QKVN + 1024 + h * 64 + ch * 8;
            uint4 kraw = *(const uint4*)(qkvh + base);
            uint4 vraw = *(const uint4*)(qkvh + base + 1024);
            __half2 kh[4], vh[4];
            memcpy(kh, &kraw, 16);
            memcpy(vh, &vraw, 16);
            #pragma unroll
            for (int t = 0; t < 4; t++) {
                float2 kf = __half22float2(kh[t]);
                int d2 = ch * 4 + t;
                *(float2*)&sKI[(d2 * 65 + j) * 2] = kf;
            }
            float2 v0 = __half22float2(vh[0]);
            float2 v1 = __half22float2(vh[1]);
            float2 v2 = __half22float2(vh[2]);
            float2 v3 = __half22float2(vh[3]);
            *(float4*)&sV[j * 64 + ch * 8]     = make_float4(v0.x, v0.y, v1.x, v1.y);
            *(float4*)&sV[j * 64 + ch * 8 + 4] = make_float4(v2.x, v2.y, v3.x, v3.y);
        }
        if (tid < 64) sBits[tid] = (c0 + tid < cnt) ? tb[c0 + tid] : 0ULL;
        __syncthreads();

        unsigned long long sa2[8], sb2[8];
        #pragma unroll
        for (int qq = 0; qq < 8; qq++) { sa2[qq] = 0ULL; sb2[qq] = 0ULL; }
        #pragma unroll
        for (int dc = 0; dc < 4; dc++) {
            unsigned long long ka[8], kb[8];
            #pragma unroll
            for (int d = 0; d < 8; d++) {
                int d2 = dc * 8 + d;
                ka[d] = *(const unsigned long long*)&sKI[(d2 * 65 + lane) * 2];
                kb[d] = *(const unsigned long long*)&sKI[(d2 * 65 + 32 + lane) * 2];
            }
            #pragma unroll
            for (int qq = 0; qq < 8; qq++) {
                const unsigned long long* qr =
                    (const unsigned long long*)&sQ[(wq0 + qq) * 64 + dc * 16];
                #pragma unroll
                for (int d = 0; d < 8; d++) {
                    unsigned long long qv = qr[d];
                    ffma2(sa2[qq], ka[d], qv);
                    ffma2(sb2[qq], kb[d], qv);
                }
            }
        }

        unsigned long long bitsA = sBits[lane];
        unsigned long long bitsB = sBits[32 + lane];
        float pa[8], pb[8];
        #pragma unroll
        for (int qq = 0; qq < 8; qq++) {
            float2 va2, vb2;
            memcpy(&va2, &sa2[qq], 8);
            memcpy(&vb2, &sb2[qq], 8);
            float va = va2.x + va2.y;
            float vb = vb2.x + vb2.y;
            pa[qq] = ((bitsA >> (wq0 + qq)) & 1ULL) ? fast_ex2(va * LOG2E) : 0.f;
            pb[qq] = ((bitsB >> (wq0 + qq)) & 1ULL) ? fast_ex2(vb * LOG2E) : 0.f;
            la[qq] += pa[qq] + pb[qq];
        }

        *(float4*)&sPw[lane * 8]            = make_float4(pa[0], pa[1], pa[2], pa[3]);
        *(float4*)&sPw[lane * 8 + 4]        = make_float4(pa[4], pa[5], pa[6], pa[7]);
        *(float4*)&sPw[(32 + lane) * 8]     = make_float4(pb[0], pb[1], pb[2], pb[3]);
        *(float4*)&sPw[(32 + lane) * 8 + 4] = make_float4(pb[4], pb[5], pb[6], pb[7]);
        __syncwarp();

        #pragma unroll 4
        for (int j = 0; j < 64; j++) {
            float4 p03 = *(const float4*)&sPw[j * 8];
            float4 p47 = *(const float4*)&sPw[j * 8 + 4];
            float2 vv = *(const float2*)&sV[j * 64 + 2 * lane];
            acc[0][0] = fmaf(p03.x, vv.x, acc[0][0]); acc[0][1] = fmaf(p03.x, vv.y, acc[0][1]);
            acc[1][0] = fmaf(p03.y, vv.x, acc[1][0]); acc[1][1] = fmaf(p03.y, vv.y, acc[1][1]);
            acc[2][0] = fmaf(p03.z, vv.x, acc[2][0]); acc[2][1] = fmaf(p03.z, vv.y, acc[2][1]);
            acc[3][0] = fmaf(p03.w, vv.x, acc[3][0]); acc[3][1] = fmaf(p03.w, vv.y, acc[3][1]);
            acc[4][0] = fmaf(p47.x, vv.x, acc[4][0]); acc[4][1] = fmaf(p47.x, vv.y, acc[4][1]);
            acc[5][0] = fmaf(p47.y, vv.x, acc[5][0]); acc[5][1] = fmaf(p47.y, vv.y, acc[5][1]);
            acc[6][0] = fmaf(p47.z, vv.x, acc[6][0]); acc[6][1] = fmaf(p47.z, vv.y, acc[6][1]);
            acc[7][0] = fmaf(p47.w, vv.x, acc[7][0]); acc[7][1] = fmaf(p47.w, vv.y, acc[7][1]);
        }
    }

    #pragma unroll
    for (int qq = 0; qq < 8; qq++) {
        float l = la[qq];
        #pragma unroll
        for (int o = 16; o; o >>= 1)
            l += __shfl_xor_sync(0xffffffffu, l, o);
        float inv = 1.f / l;
        size_t o = (size_t)(b * Sq + q0 + wq0 + qq) * Eq + h * 64 + 2 * lane;
        __half2 hv = __floats2half2_rn(acc[qq][0] * inv, acc[qq][1] * inv);
        *(__half2*)(out + o) = hv;
    }
}

// ---------------- host ----------------
extern "C" void kernel_launch(void* const* d_in, const int* in_sizes, int n_in,
                              void* d_out, int out_size) {
    const float* x      = (const float*)d_in[0];
    const float* ln1_g  = (const float*)d_in[1];
    const float* ln1_b  = (const float*)d_in[2];
    const float* ln2_g  = (const float*)d_in[3];
    const float* ln2_b  = (const float*)d_in[4];
    const float* wq     = (const float*)d_in[5];
    const float* bq     = (const float*)d_in[6];
    const float* wk     = (const float*)d_in[7];
    const float* bk     = (const float*)d_in[8];
    const float* wv     = (const float*)d_in[9];
    const float* bv     = (const float*)d_in[10];
    const float* wo     = (const float*)d_in[11];
    const float* bo     = (const float*)d_in[12];
    const float* w_fc   = (const float*)d_in[13];
    const float* b_fc   = (const float*)d_in[14];
    const float* w_proj = (const float*)d_in[15];
    const float* b_proj = (const float*)d_in[16];
    const unsigned char* mask = (const unsigned char*)d_in[17];
    float* out = (float*)d_out;

    float *h, *hr, *qkv, *attn, *t, *u, *w, *bqkv;
    cudaGetSymbolAddress((void**)&h,    g_h);
    cudaGetSymbolAddress((void**)&hr,   g_hr);
    cudaGetSymbolAddress((void**)&qkv,  g_qkv);
    cudaGetSymbolAddress((void**)&attn, g_attn);
    cudaGetSymbolAddress((void**)&t,    g_t);
    cudaGetSymbolAddress((void**)&u,    g_u);
    cudaGetSymbolAddress((void**)&w,    g_w);
    cudaGetSymbolAddress((void**)&bqkv, g_bias);

    __half* hr_h   = (__half*)hr;
    __half* qkv_h  = (__half*)qkv;
    __half* attn_h = (__half*)attn;
    __half* t_h    = (__half*)t;
    __half* u_h    = (__half*)u;
    __half* wh     = (__half*)w;

    const size_t EE = (size_t)Eq * Eq;
    __half* wqkv_h = wh;             // [3072,1024]: wq*scale || wk || wv
    __half* wo_h   = wh + 3 * EE;
    __half* wfc_h  = wh + 4 * EE;
    __half* wpr_h  = wh + 8 * EE;

    cudaFuncSetAttribute(gemm_f16_kernel,
                         cudaFuncAttributeMaxDynamicSharedMemorySize, GEMM_SMEM);
    cudaFuncSetAttribute(attn_tile_kernel,
                         cudaFuncAttributeMaxDynamicSharedMemorySize, ATT_SMEM);

    convert_w_kernel<<<3 * 1024 * 1024 / 256, 256>>>(wq, wk, wv, wo, w_fc, w_proj,
                                                     bq, bk, bv, wh);
    tile_build_kernel<<<NT, 256>>>(mask);
    ln_kernel<<<BSq, 256>>>(x, ln1_g, ln1_b, h, hr_h);

    // fused QKV projection (scale folded into wq/bq), half output
    dim3 gQKV(QKVN / 256, BSq / 128);  // (12, 64)
    gemm_f16_kernel<<<gQKV, 256, GEMM_SMEM>>>(hr_h, wqkv_h, bqkv, nullptr, nullptr, qkv_h,
                                              BSq, QKVN, Eq, 0);

    attn_tile_kernel<<<dim3(NT, Hn, Bq), 256, ATT_SMEM>>>(qkv_h, attn_h);

    dim3 gEE(Eq / 256, BSq / 128);     // (4, 64)
    gemm_f16_kernel<<<gEE, 256, GEMM_SMEM>>>(attn_h, wo_h, bo, h, out, nullptr,
                                             BSq, Eq, Eq, 0);

    ln_kernel<<<BSq, 256>>>(out, ln2_g, ln2_b, nullptr, t_h);

    dim3 gFC(FEq / 256, BSq / 128);    // (16, 64)
    gemm_f16_kernel<<<gFC, 256, GEMM_SMEM>>>(t_h, wfc_h, b_fc, nullptr, nullptr, u_h,
                                             BSq, FEq, Eq, 1);

    gemm_f16_kernel<<<gEE, 256, GEMM_SMEM>>>(u_h, wpr_h, b_proj, out, out, nullptr,
                                             BSq, Eq, FEq, 0);
}